// round 13
// baseline (speedup 1.0000x reference)
#include <cuda_runtime.h>
#include <cuda_fp16.h>
#include <cstdint>

// Problem constants
#define N_V   50000
#define R_    5
#define A_    8
#define RA    40
#define C_    64
#define NCOL  512
#define CH_N  82              // 32-k chunks total: g0:22 (K=704), g1-3:20 (K=640)
#define MB_N  391             // ceil(50048/128)
#define SQ2   0.70710678118654752f

// Scratch (static device arrays — no cudaMalloc allowed)
__device__ __half g_msh[(size_t)N_V * C_];               // 6.4 MB fp16 mesh signal
__device__ __half g_Afrag[(size_t)MB_N * CH_N * 4096];   // ~262 MB freq-domain A frags
__device__ __half g_Bfrag[(size_t)CH_N * 4096];          // 672 KB freq-domain B frags
__device__ float  g_P[(size_t)MB_N * 128 * 512];         // ~102 MB partial products

__device__ __forceinline__ uint32_t smem_u32(const void* p) {
    uint32_t a;
    asm("{ .reg .u64 t; cvta.to.shared.u64 t, %1; cvt.u32.u64 %0, t; }" : "=r"(a) : "l"(p));
    return a;
}
__device__ __forceinline__ int grp_cb(int g) { return g == 0 ? 0 : 2 + g * 20; }

// K-pre: fp32 -> fp16 mesh signal.
__global__ void convert_ms_kernel(const float* __restrict__ ms)
{
    int i = blockIdx.x * 256 + threadIdx.x;      // half2 index
    if (i < N_V * 32) {
        float2 v = ((const float2*)ms)[i];
        ((__half2*)g_msh)[i] = __floats2half2_rn(v.x, v.y);
    }
}

// 8-point real FFT, e^{-i2*pi*f*a/8}. out: r0,r4,r1,i1,r2,i2,r3,i3
__device__ __forceinline__ void fft8(float x0, float x1, float x2, float x3,
                                     float x4, float x5, float x6, float x7,
                                     float* o)
{
    float a04 = x0 + x4, s04 = x0 - x4;
    float a26 = x2 + x6, s26 = x2 - x6;
    float a15 = x1 + x5, s15 = x1 - x5;
    float a37 = x3 + x7, s37 = x3 - x7;
    o[0] = a04 + a26 + a15 + a37;
    o[1] = a04 + a26 - a15 - a37;
    float u = SQ2 * (s15 - s37);
    float w = SQ2 * (s15 + s37);
    o[2] = s04 + u;
    o[3] = -(w + s26);
    o[4] = a04 - a26;
    o[5] = -(a15 - a37);
    o[6] = s04 - u;
    o[7] = -(w - s26);
}

// B fragment half index
__device__ __forceinline__ size_t bfrag_idx(int cb, int klocal, int j) {
    int kt = klocal >> 5, kl = klocal & 31;
    int kk = kl >> 4, kb = kl & 15;
    int r = kb >> 3, rem = kb & 7, t4 = rem >> 1, e = rem & 1;
    int NT = j >> 3, gn = j & 7;
    int ln = gn * 4 + t4;
    return (size_t)(cb + kt) * 4096 + (size_t)(((NT * 2 + kk) * 32 + ln) * 4 + r * 2 + e);
}

// ---------------------------------------------------------------------------
// K0: fold prior into V (= Weff at o=0), rFFT over alpha, write B fragments.
// ---------------------------------------------------------------------------
__global__ void build_V_kernel(const float* __restrict__ nw,
                               const float* __restrict__ cw,
                               const float* __restrict__ coeff)
{
    int t = blockIdx.x;
    int c = threadIdx.x;

    __shared__ float s_coeff[R_ * A_ * RA];
    for (int i = c; i < R_ * A_ * RA; i += 64) s_coeff[i] = coeff[i];
    __syncthreads();

    float wv[R_][A_];
    #pragma unroll
    for (int r = 0; r < R_; r++)
        #pragma unroll
        for (int a = 0; a < A_; a++)
            wv[r][a] = nw[(((size_t)t * R_ + r) * A_ + a) * C_ + c];

    float v[RA];
    for (int m = 0; m < RA; m++) {
        float acc = 0.f;
        #pragma unroll
        for (int r = 0; r < R_; r++)
            #pragma unroll
            for (int a = 0; a < A_; a++)
                acc += s_coeff[(r * A_ + a) * RA + m] * wv[r][a];
        v[m] = acc;
    }

    #pragma unroll
    for (int rho = 0; rho < R_; rho++) {
        float o[8];
        fft8(v[rho * 8 + 0], v[rho * 8 + 1], v[rho * 8 + 2], v[rho * 8 + 3],
             v[rho * 8 + 4], v[rho * 8 + 5], v[rho * 8 + 6], v[rho * 8 + 7], o);
        int kb = rho * 64 + c;
        __half zero = __float2half_rn(0.f);
        g_Bfrag[bfrag_idx(0, kb,       t     )] = __float2half_rn(o[0]);
        g_Bfrag[bfrag_idx(0, 320 + kb, t     )] = zero;
        g_Bfrag[bfrag_idx(0, kb,       64 + t)] = zero;
        g_Bfrag[bfrag_idx(0, 320 + kb, 64 + t)] = __float2half_rn(o[1]);
        #pragma unroll
        for (int f = 1; f <= 3; f++) {
            float vr = o[f * 2], vi = o[f * 2 + 1];
            int cb = grp_cb(f);
            g_Bfrag[bfrag_idx(cb, kb,       t     )] = __float2half_rn(vr);
            g_Bfrag[bfrag_idx(cb, 320 + kb, t     )] = __float2half_rn(vi);
            g_Bfrag[bfrag_idx(cb, kb,       64 + t)] = __float2half_rn(vi);
            g_Bfrag[bfrag_idx(cb, 320 + kb, 64 + t)] = __float2half_rn(-vr);
        }
    }
    g_Bfrag[bfrag_idx(0, 640 + c, t     )] = __float2half_rn(8.f * cw[t * C_ + c]);
    g_Bfrag[bfrag_idx(0, 640 + c, 64 + t)] = __float2half_rn(0.f);
}

// ---------------------------------------------------------------------------
// K1: fp16 gather -> register FFT -> fp16 A-fragments.
// One block per vertex PAIR (n, n+8), 512 threads = 16 warps.
// Warp roles by (v = tid>>8, rho = (tid&255)>>5): rho<5 -> FFT warp (lane=cp),
// rho==5 -> center warp, rho 6,7 idle. One sync, then fragment writes.
// ---------------------------------------------------------------------------
__global__ __launch_bounds__(512)
void build_X_kernel(const float* __restrict__ bary)
{
    int bp = blockIdx.x;
    int mb = bp >> 6;
    int q  = bp & 63;
    int MT = q >> 3;
    int gl = q & 7;
    int n0 = mb * 128 + MT * 16 + gl;

    __shared__ float s_row[2][2624];
    __shared__ float sb[2][240];
    int tid = threadIdx.x;
    int v   = tid >> 8;
    int t   = tid & 255;
    int n   = n0 + 8 * v;
    bool ok = n < N_V;

    if (t < 240) sb[v][t] = ok ? bary[(size_t)n * 240 + t] : 0.f;
    __syncthreads();

    int rho = t >> 5;              // 0..7
    int cp  = t & 31;              // channel pair
    const __half2* msh2 = (const __half2*)g_msh;

    if (rho < 5) {
        float xc0[8], xc1[8];
        if (ok) {
            // issue all 24 gathers with high MLP
            __half2 h0[8], h1[8], h2[8];
            float w0[8], w1[8], w2[8];
            #pragma unroll
            for (int a = 0; a < 8; a++) {
                int m = rho * 8 + a;
                int i0 = (int)sb[v][m * 6 + 0]; w0[a] = sb[v][m * 6 + 1];
                int i1 = (int)sb[v][m * 6 + 2]; w1[a] = sb[v][m * 6 + 3];
                int i2 = (int)sb[v][m * 6 + 4]; w2[a] = sb[v][m * 6 + 5];
                h0[a] = msh2[(size_t)i0 * 32 + cp];
                h1[a] = msh2[(size_t)i1 * 32 + cp];
                h2[a] = msh2[(size_t)i2 * 32 + cp];
            }
            #pragma unroll
            for (int a = 0; a < 8; a++) {
                float2 x0 = __half22float2(h0[a]);
                float2 x1 = __half22float2(h1[a]);
                float2 x2 = __half22float2(h2[a]);
                xc0[a] = w0[a] * x0.x + w1[a] * x1.x + w2[a] * x2.x;
                xc1[a] = w0[a] * x0.y + w1[a] * x1.y + w2[a] * x2.y;
            }
        } else {
            #pragma unroll
            for (int a = 0; a < 8; a++) { xc0[a] = 0.f; xc1[a] = 0.f; }
        }
        float o0[8], o1[8];
        fft8(xc0[0], xc0[1], xc0[2], xc0[3], xc0[4], xc0[5], xc0[6], xc0[7], o0);
        fft8(xc1[0], xc1[1], xc1[2], xc1[3], xc1[4], xc1[5], xc1[6], xc1[7], o1);
        int base = rho * 64 + cp * 2;
        *(float2*)&s_row[v][base]        = make_float2(o0[0], o1[0]);   // Xr0
        *(float2*)&s_row[v][320 + base]  = make_float2(o0[1], o1[1]);   // Xr4
        *(float2*)&s_row[v][704 + base]  = make_float2(o0[2], o1[2]);   // Xr1
        *(float2*)&s_row[v][1024 + base] = make_float2(o0[3], o1[3]);   // Xi1
        *(float2*)&s_row[v][1344 + base] = make_float2(o0[4], o1[4]);   // Xr2
        *(float2*)&s_row[v][1664 + base] = make_float2(o0[5], o1[5]);   // Xi2
        *(float2*)&s_row[v][1984 + base] = make_float2(o0[6], o1[6]);   // Xr3
        *(float2*)&s_row[v][2304 + base] = make_float2(o0[7], o1[7]);   // Xi3
    } else if (rho == 5) {
        float2 cme = ok ? __half22float2(msh2[(size_t)n * 32 + cp])
                        : make_float2(0.f, 0.f);
        *(float2*)&s_row[v][640 + cp * 2] = cme;
    }
    __syncthreads();

    // fragment write: 82 chunks x 8 (kk,t4) uint4 per vertex pair
    for (int w = tid; w < CH_N * 8; w += 512) {
        int kt = w >> 3;
        int kk = (w >> 2) & 1;
        int t4 = w & 3;
        int k0 = kt * 32 + kk * 16 + t4 * 2;
        __half2 x = __floats2half2_rn(s_row[0][k0],     s_row[0][k0 + 1]);
        __half2 y = __floats2half2_rn(s_row[1][k0],     s_row[1][k0 + 1]);
        __half2 z = __floats2half2_rn(s_row[0][k0 + 8], s_row[0][k0 + 9]);
        __half2 u = __floats2half2_rn(s_row[1][k0 + 8], s_row[1][k0 + 9]);
        uint4 val;
        val.x = *(uint32_t*)&x; val.y = *(uint32_t*)&y;
        val.z = *(uint32_t*)&z; val.w = *(uint32_t*)&u;
        ((uint4*)(g_Afrag + ((size_t)mb * CH_N + kt) * 4096))
            [(MT * 2 + kk) * 32 + gl * 4 + t4] = val;
    }
}

// ---------------------------------------------------------------------------
// K2: per-frequency fp16 GEMM -> partial products P. (unchanged)
// ---------------------------------------------------------------------------
__device__ __forceinline__ void mma_f16(float* c, uint32_t a0, uint32_t a1,
                                        uint32_t a2, uint32_t a3,
                                        uint32_t b0, uint32_t b1)
{
    asm volatile(
        "mma.sync.aligned.m16n8k16.row.col.f32.f16.f16.f32 "
        "{%0,%1,%2,%3}, {%4,%5,%6,%7}, {%8,%9}, {%0,%1,%2,%3};\n"
        : "+f"(c[0]), "+f"(c[1]), "+f"(c[2]), "+f"(c[3])
        : "r"(a0), "r"(a1), "r"(a2), "r"(a3), "r"(b0), "r"(b1));
}
__device__ __forceinline__ void cp16(uint32_t s, const void* g) {
    asm volatile("cp.async.cg.shared.global [%0], [%1], 16;" :: "r"(s), "l"(g));
}

#define STAGE_BYTES 16384
#define NSTAGE      4
#define SMEM_TOTAL  (NSTAGE * STAGE_BYTES)   // 64KB

__global__ __launch_bounds__(256, 2)
void gemm_kernel()
{
    extern __shared__ char smem[];
    uint32_t sbase = smem_u32(smem);

    int tid  = threadIdx.x;
    int warp = tid >> 5;
    int ln   = tid & 31;
    int wm   = warp >> 2;
    int wn   = warp & 3;
    int grp  = blockIdx.x;
    int mb   = blockIdx.y;

    int cb  = grp_cb(grp);
    int ktn = (grp == 0) ? 22 : 20;

    const uint4* Ag = (const uint4*)(g_Afrag + ((size_t)mb * CH_N + cb) * 4096);
    const uint4* Bg = (const uint4*)(g_Bfrag + (size_t)cb * 4096);

    auto issue = [&](int s) {
        uint32_t dst = sbase + (uint32_t)(s & (NSTAGE - 1)) * STAGE_BYTES;
        const uint4* As = Ag + (size_t)s * 512;
        cp16(dst + tid * 16, As + tid);
        cp16(dst + (tid + 256) * 16, As + tid + 256);
        const uint4* Bs = Bg + (size_t)s * 512;
        cp16(dst + 8192 + tid * 16, Bs + tid);
        cp16(dst + 8192 + (tid + 256) * 16, Bs + tid + 256);
    };

    issue(0);
    asm volatile("cp.async.commit_group;" ::: "memory");
    issue(1);
    asm volatile("cp.async.commit_group;" ::: "memory");
    issue(2);
    asm volatile("cp.async.commit_group;" ::: "memory");

    float acc[4][4][4];
    #pragma unroll
    for (int mt = 0; mt < 4; mt++)
        #pragma unroll
        for (int nt = 0; nt < 4; nt++)
            #pragma unroll
            for (int i = 0; i < 4; i++) acc[mt][nt][i] = 0.f;

    for (int kt = 0; kt < ktn; kt++) {
        asm volatile("cp.async.wait_group 2;" ::: "memory");
        __syncthreads();

        if (kt + 3 < ktn) issue(kt + 3);
        asm volatile("cp.async.commit_group;" ::: "memory");

        uint32_t bufA = sbase + (uint32_t)(kt & (NSTAGE - 1)) * STAGE_BYTES;
        uint32_t bufB = bufA + 8192;

        #pragma unroll
        for (int kk = 0; kk < 2; kk++) {
            uint4 af[4];
            uint2 bf[4];
            #pragma unroll
            for (int mt = 0; mt < 4; mt++) {
                uint32_t a = bufA + ((((wm * 4 + mt) * 2 + kk) * 32 + ln) * 16);
                asm volatile("ld.shared.v4.b32 {%0,%1,%2,%3}, [%4];"
                             : "=r"(af[mt].x), "=r"(af[mt].y), "=r"(af[mt].z), "=r"(af[mt].w)
                             : "r"(a));
            }
            #pragma unroll
            for (int nt = 0; nt < 4; nt++) {
                int NT = wn * 4 + nt;
                uint32_t b = bufB + (((NT * 2 + kk) * 32 + ln) * 8);
                asm volatile("ld.shared.v2.b32 {%0,%1}, [%2];"
                             : "=r"(bf[nt].x), "=r"(bf[nt].y) : "r"(b));
            }
            #pragma unroll
            for (int mt = 0; mt < 4; mt++)
                #pragma unroll
                for (int nt = 0; nt < 4; nt++)
                    mma_f16(acc[mt][nt], af[mt].x, af[mt].y, af[mt].z, af[mt].w,
                            bf[nt].x, bf[nt].y);
        }
    }

    int g_  = ln >> 2;
    int t4  = ln & 3;
    #pragma unroll
    for (int nt = 0; nt < 4; nt++) {
        int col = grp * 128 + wn * 32 + nt * 8 + t4 * 2;
        #pragma unroll
        for (int mt = 0; mt < 4; mt++) {
            int row0 = mb * 128 + wm * 64 + mt * 16 + g_;
            if (row0 < N_V)
                *(float2*)(g_P + (size_t)row0 * 512 + col) =
                    make_float2(acc[mt][nt][0], acc[mt][nt][1]);
            if (row0 + 8 < N_V)
                *(float2*)(g_P + (size_t)(row0 + 8) * 512 + col) =
                    make_float2(acc[mt][nt][2], acc[mt][nt][3]);
        }
    }
}

// ---------------------------------------------------------------------------
// K3: inverse angular DFT combine + bias + relu.
// ---------------------------------------------------------------------------
__global__ __launch_bounds__(256)
void combine_kernel(const float* __restrict__ bias, float* __restrict__ out)
{
    int gidx = blockIdx.x * 256 + threadIdx.x;
    int n = gidx >> 6;
    int t = gidx & 63;
    if (n >= N_V) return;

    const float* P = g_P + (size_t)n * 512;
    float P0 = P[t],        P4 = P[64 + t];
    float R1 = P[128 + t],  I1 = P[192 + t];
    float R2 = P[256 + t],  I2 = P[320 + t];
    float R3 = P[384 + t],  I3 = P[448 + t];
    float b = bias[t];

    const float CO1[8] = {1.f, SQ2, 0.f, -SQ2, -1.f, -SQ2, 0.f, SQ2};
    const float SI1[8] = {0.f, SQ2, 1.f, SQ2, 0.f, -SQ2, -1.f, -SQ2};
    const float CO2[8] = {1.f, 0.f, -1.f, 0.f, 1.f, 0.f, -1.f, 0.f};
    const float SI2[8] = {0.f, 1.f, 0.f, -1.f, 0.f, 1.f, 0.f, -1.f};
    const float CO3[8] = {1.f, -SQ2, 0.f, SQ2, -1.f, SQ2, 0.f, -SQ2};
    const float SI3[8] = {0.f, SQ2, -1.f, SQ2, 0.f, -SQ2, 1.f, -SQ2};

    float* orow = out + (size_t)n * NCOL;
    #pragma unroll
    for (int o = 0; o < 8; o++) {
        float sgn = (o & 1) ? -1.f : 1.f;
        float val = 0.125f * (P0 + sgn * P4
                    + 2.f * (R1 * CO1[o] - I1 * SI1[o]
                           + R2 * CO2[o] - I2 * SI2[o]
                           + R3 * CO3[o] - I3 * SI3[o])) + b;
        orow[o * 64 + t] = val > 0.f ? val : 0.f;
    }
}

// ---------------------------------------------------------------------------
// Launch order: convert, build_V, build_X, gemm, combine
// Inputs: mesh_signal, bary_coordinates, neighbor_weights, center_weights,
//         bias, interp_coeff
// ---------------------------------------------------------------------------
extern "C" void kernel_launch(void* const* d_in, const int* in_sizes, int n_in,
                              void* d_out, int out_size)
{
    const float* ms    = (const float*)d_in[0];
    const float* bary  = (const float*)d_in[1];
    const float* nw    = (const float*)d_in[2];
    const float* cw    = (const float*)d_in[3];
    const float* bias  = (const float*)d_in[4];
    const float* coeff = (const float*)d_in[5];
    float* out = (float*)d_out;

    cudaFuncSetAttribute(gemm_kernel,
                         cudaFuncAttributeMaxDynamicSharedMemorySize, SMEM_TOTAL);

    convert_ms_kernel<<<(N_V * 32 + 255) / 256, 256>>>(ms);
    build_V_kernel<<<64, 64>>>(nw, cw, coeff);
    build_X_kernel<<<MB_N * 64, 512>>>(bary);

    dim3 grid(4, MB_N);
    gemm_kernel<<<grid, 256, SMEM_TOTAL>>>();

    combine_kernel<<<(N_V * 64 + 255) / 256, 256>>>(bias, out);
}

// round 15
// speedup vs baseline: 1.0151x; 1.0151x over previous
#include <cuda_runtime.h>
#include <cuda_fp16.h>
#include <cstdint>

// Problem constants
#define N_V   50000
#define R_    5
#define A_    8
#define RA    40
#define C_    64
#define NCOL  512
#define CH_N  82              // 32-k chunks total: g0:22 (K=704), g1-3:20 (K=640)
#define MB_N  391             // ceil(50048/128)
#define SQ2   0.70710678118654752f

// Scratch (static device arrays — no cudaMalloc allowed)
__device__ __half g_msh[(size_t)N_V * C_];               // 6.4 MB fp16 mesh signal
__device__ __half g_Afrag[(size_t)MB_N * CH_N * 4096];   // ~262 MB freq-domain A frags
__device__ __half g_Bfrag[(size_t)CH_N * 4096];          // 672 KB freq-domain B frags
__device__ float  g_P[(size_t)MB_N * 128 * 512];         // ~102 MB partial products

__device__ __forceinline__ uint32_t smem_u32(const void* p) {
    uint32_t a;
    asm("{ .reg .u64 t; cvta.to.shared.u64 t, %1; cvt.u32.u64 %0, t; }" : "=r"(a) : "l"(p));
    return a;
}
__device__ __forceinline__ int grp_cb(int g) { return g == 0 ? 0 : 2 + g * 20; }

// Dummy: shifts ncu capture slot (our 4th launch) onto build_X this round.
__global__ void dummy_kernel() {}

// K-pre: fp32 -> fp16 mesh signal.
__global__ void convert_ms_kernel(const float* __restrict__ ms)
{
    int i = blockIdx.x * 256 + threadIdx.x;      // half2 index
    if (i < N_V * 32) {
        float2 v = ((const float2*)ms)[i];
        ((__half2*)g_msh)[i] = __floats2half2_rn(v.x, v.y);
    }
}

// 8-point real FFT, e^{-i2*pi*f*a/8}. out: r0,r4,r1,i1,r2,i2,r3,i3
__device__ __forceinline__ void fft8(float x0, float x1, float x2, float x3,
                                     float x4, float x5, float x6, float x7,
                                     float* o)
{
    float a04 = x0 + x4, s04 = x0 - x4;
    float a26 = x2 + x6, s26 = x2 - x6;
    float a15 = x1 + x5, s15 = x1 - x5;
    float a37 = x3 + x7, s37 = x3 - x7;
    o[0] = a04 + a26 + a15 + a37;
    o[1] = a04 + a26 - a15 - a37;
    float u = SQ2 * (s15 - s37);
    float w = SQ2 * (s15 + s37);
    o[2] = s04 + u;
    o[3] = -(w + s26);
    o[4] = a04 - a26;
    o[5] = -(a15 - a37);
    o[6] = s04 - u;
    o[7] = -(w - s26);
}

// B fragment half index
__device__ __forceinline__ size_t bfrag_idx(int cb, int klocal, int j) {
    int kt = klocal >> 5, kl = klocal & 31;
    int kk = kl >> 4, kb = kl & 15;
    int r = kb >> 3, rem = kb & 7, t4 = rem >> 1, e = rem & 1;
    int NT = j >> 3, gn = j & 7;
    int ln = gn * 4 + t4;
    return (size_t)(cb + kt) * 4096 + (size_t)(((NT * 2 + kk) * 32 + ln) * 4 + r * 2 + e);
}

// ---------------------------------------------------------------------------
// K0: fold prior into V (= Weff at o=0), rFFT over alpha, write B fragments.
// ---------------------------------------------------------------------------
__global__ void build_V_kernel(const float* __restrict__ nw,
                               const float* __restrict__ cw,
                               const float* __restrict__ coeff)
{
    int t = blockIdx.x;
    int c = threadIdx.x;

    __shared__ float s_coeff[R_ * A_ * RA];
    for (int i = c; i < R_ * A_ * RA; i += 64) s_coeff[i] = coeff[i];
    __syncthreads();

    float wv[R_][A_];
    #pragma unroll
    for (int r = 0; r < R_; r++)
        #pragma unroll
        for (int a = 0; a < A_; a++)
            wv[r][a] = nw[(((size_t)t * R_ + r) * A_ + a) * C_ + c];

    float v[RA];
    for (int m = 0; m < RA; m++) {
        float acc = 0.f;
        #pragma unroll
        for (int r = 0; r < R_; r++)
            #pragma unroll
            for (int a = 0; a < A_; a++)
                acc += s_coeff[(r * A_ + a) * RA + m] * wv[r][a];
        v[m] = acc;
    }

    #pragma unroll
    for (int rho = 0; rho < R_; rho++) {
        float o[8];
        fft8(v[rho * 8 + 0], v[rho * 8 + 1], v[rho * 8 + 2], v[rho * 8 + 3],
             v[rho * 8 + 4], v[rho * 8 + 5], v[rho * 8 + 6], v[rho * 8 + 7], o);
        int kb = rho * 64 + c;
        __half zero = __float2half_rn(0.f);
        g_Bfrag[bfrag_idx(0, kb,       t     )] = __float2half_rn(o[0]);
        g_Bfrag[bfrag_idx(0, 320 + kb, t     )] = zero;
        g_Bfrag[bfrag_idx(0, kb,       64 + t)] = zero;
        g_Bfrag[bfrag_idx(0, 320 + kb, 64 + t)] = __float2half_rn(o[1]);
        #pragma unroll
        for (int f = 1; f <= 3; f++) {
            float vr = o[f * 2], vi = o[f * 2 + 1];
            int cb = grp_cb(f);
            g_Bfrag[bfrag_idx(cb, kb,       t     )] = __float2half_rn(vr);
            g_Bfrag[bfrag_idx(cb, 320 + kb, t     )] = __float2half_rn(vi);
            g_Bfrag[bfrag_idx(cb, kb,       64 + t)] = __float2half_rn(vi);
            g_Bfrag[bfrag_idx(cb, 320 + kb, 64 + t)] = __float2half_rn(-vr);
        }
    }
    g_Bfrag[bfrag_idx(0, 640 + c, t     )] = __float2half_rn(8.f * cw[t * C_ + c]);
    g_Bfrag[bfrag_idx(0, 640 + c, 64 + t)] = __float2half_rn(0.f);
}

// ---------------------------------------------------------------------------
// K1 (R11 staged version + streaming frag stores):
// fp16 barycentric gather -> smem -> angular rFFT -> fp16 A-fragments.
// One block per vertex PAIR (n, n+8), 512 threads (bit 8 = vertex).
// ---------------------------------------------------------------------------
__global__ __launch_bounds__(512)
void build_X_kernel(const float* __restrict__ bary)
{
    int bp = blockIdx.x;
    int mb = bp >> 6;
    int q  = bp & 63;
    int MT = q >> 3;
    int gl = q & 7;
    int n0 = mb * 128 + MT * 16 + gl;

    __shared__ float s_row[2][2624];
    __shared__ float sb[2][240];
    int tid = threadIdx.x;
    int v   = tid >> 8;
    int t   = tid & 255;
    int n   = n0 + 8 * v;

    if (t < 240) sb[v][t] = (n < N_V) ? bary[(size_t)n * 240 + t] : 0.f;
    __syncthreads();

    if (n < N_V) {
        int g8 = t >> 5;            // 0..7 m-group
        int cp = t & 31;            // channel pair 0..31
        const __half2* msh2 = (const __half2*)g_msh;
        #pragma unroll
        for (int it = 0; it < 5; it++) {
            int m  = it * 8 + g8;
            int i0 = (int)sb[v][m * 6 + 0]; float w0 = sb[v][m * 6 + 1];
            int i1 = (int)sb[v][m * 6 + 2]; float w1 = sb[v][m * 6 + 3];
            int i2 = (int)sb[v][m * 6 + 4]; float w2 = sb[v][m * 6 + 5];
            float2 x0 = __half22float2(msh2[(size_t)i0 * 32 + cp]);
            float2 x1 = __half22float2(msh2[(size_t)i1 * 32 + cp]);
            float2 x2 = __half22float2(msh2[(size_t)i2 * 32 + cp]);
            float2 r;
            r.x = w0 * x0.x + w1 * x1.x + w2 * x2.x;
            r.y = w0 * x0.y + w1 * x1.y + w2 * x2.y;
            *(float2*)&s_row[v][m * C_ + cp * 2] = r;
        }
        if (g8 == 0) {
            float2 cme = __half22float2(msh2[(size_t)n * 32 + cp]);
            *(float2*)&s_row[v][2560 + cp * 2] = cme;
        }
    } else {
        for (int i = t; i < 2624; i += 256) s_row[v][i] = 0.f;
    }
    __syncthreads();

    // FFT pass (tasks 0..319 = FFT over alpha; 320..383 move center rows)
    float rg[2][8];
    #pragma unroll
    for (int p = 0; p < 2; p++) {
        int task = t + p * 256;
        if (task < 320) {
            int rho = task >> 6, c = task & 63;
            const float* x = &s_row[v][rho * 512 + c];
            fft8(x[0], x[64], x[128], x[192], x[256], x[320], x[384], x[448], rg[p]);
        } else if (task < 384) {
            rg[p][0] = s_row[v][2560 + (task - 320)];
        }
    }
    __syncthreads();
    #pragma unroll
    for (int p = 0; p < 2; p++) {
        int task = t + p * 256;
        if (task < 320) {
            int rho = task >> 6, c = task & 63;
            int base = rho * 64 + c;
            s_row[v][base]        = rg[p][0];   // Xr0
            s_row[v][320 + base]  = rg[p][1];   // Xr4
            s_row[v][704 + base]  = rg[p][2];   // Xr1
            s_row[v][1024 + base] = rg[p][3];   // Xi1
            s_row[v][1344 + base] = rg[p][4];   // Xr2
            s_row[v][1664 + base] = rg[p][5];   // Xi2
            s_row[v][1984 + base] = rg[p][6];   // Xr3
            s_row[v][2304 + base] = rg[p][7];   // Xi3
        } else if (task < 384) {
            s_row[v][640 + (task - 320)] = rg[p][0];
        }
    }
    __syncthreads();

    // fragment write: 82 chunks x 8 (kk,t4) uint4 per vertex pair.
    // st.global.cs: evict-first, keep g_msh / bary resident in L2.
    for (int w = tid; w < CH_N * 8; w += 512) {
        int kt = w >> 3;
        int kk = (w >> 2) & 1;
        int t4 = w & 3;
        int k0 = kt * 32 + kk * 16 + t4 * 2;
        __half2 x = __floats2half2_rn(s_row[0][k0],     s_row[0][k0 + 1]);
        __half2 y = __floats2half2_rn(s_row[1][k0],     s_row[1][k0 + 1]);
        __half2 z = __floats2half2_rn(s_row[0][k0 + 8], s_row[0][k0 + 9]);
        __half2 u = __floats2half2_rn(s_row[1][k0 + 8], s_row[1][k0 + 9]);
        uint4* dst = ((uint4*)(g_Afrag + ((size_t)mb * CH_N + kt) * 4096))
                     + ((MT * 2 + kk) * 32 + gl * 4 + t4);
        asm volatile("st.global.cs.v4.b32 [%0], {%1,%2,%3,%4};"
                     :: "l"(dst), "r"(*(uint32_t*)&x), "r"(*(uint32_t*)&y),
                        "r"(*(uint32_t*)&z), "r"(*(uint32_t*)&u) : "memory");
    }
}

// ---------------------------------------------------------------------------
// K2: per-frequency fp16 GEMM -> partial products P. (unchanged)
// ---------------------------------------------------------------------------
__device__ __forceinline__ void mma_f16(float* c, uint32_t a0, uint32_t a1,
                                        uint32_t a2, uint32_t a3,
                                        uint32_t b0, uint32_t b1)
{
    asm volatile(
        "mma.sync.aligned.m16n8k16.row.col.f32.f16.f16.f32 "
        "{%0,%1,%2,%3}, {%4,%5,%6,%7}, {%8,%9}, {%0,%1,%2,%3};\n"
        : "+f"(c[0]), "+f"(c[1]), "+f"(c[2]), "+f"(c[3])
        : "r"(a0), "r"(a1), "r"(a2), "r"(a3), "r"(b0), "r"(b1));
}
__device__ __forceinline__ void cp16(uint32_t s, const void* g) {
    asm volatile("cp.async.cg.shared.global [%0], [%1], 16;" :: "r"(s), "l"(g));
}

#define STAGE_BYTES 16384
#define NSTAGE      4
#define SMEM_TOTAL  (NSTAGE * STAGE_BYTES)   // 64KB

__global__ __launch_bounds__(256, 2)
void gemm_kernel()
{
    extern __shared__ char smem[];
    uint32_t sbase = smem_u32(smem);

    int tid  = threadIdx.x;
    int warp = tid >> 5;
    int ln   = tid & 31;
    int wm   = warp >> 2;
    int wn   = warp & 3;
    int grp  = blockIdx.x;
    int mb   = blockIdx.y;

    int cb  = grp_cb(grp);
    int ktn = (grp == 0) ? 22 : 20;

    const uint4* Ag = (const uint4*)(g_Afrag + ((size_t)mb * CH_N + cb) * 4096);
    const uint4* Bg = (const uint4*)(g_Bfrag + (size_t)cb * 4096);

    auto issue = [&](int s) {
        uint32_t dst = sbase + (uint32_t)(s & (NSTAGE - 1)) * STAGE_BYTES;
        const uint4* As = Ag + (size_t)s * 512;
        cp16(dst + tid * 16, As + tid);
        cp16(dst + (tid + 256) * 16, As + tid + 256);
        const uint4* Bs = Bg + (size_t)s * 512;
        cp16(dst + 8192 + tid * 16, Bs + tid);
        cp16(dst + 8192 + (tid + 256) * 16, Bs + tid + 256);
    };

    issue(0);
    asm volatile("cp.async.commit_group;" ::: "memory");
    issue(1);
    asm volatile("cp.async.commit_group;" ::: "memory");
    issue(2);
    asm volatile("cp.async.commit_group;" ::: "memory");

    float acc[4][4][4];
    #pragma unroll
    for (int mt = 0; mt < 4; mt++)
        #pragma unroll
        for (int nt = 0; nt < 4; nt++)
            #pragma unroll
            for (int i = 0; i < 4; i++) acc[mt][nt][i] = 0.f;

    for (int kt = 0; kt < ktn; kt++) {
        asm volatile("cp.async.wait_group 2;" ::: "memory");
        __syncthreads();

        if (kt + 3 < ktn) issue(kt + 3);
        asm volatile("cp.async.commit_group;" ::: "memory");

        uint32_t bufA = sbase + (uint32_t)(kt & (NSTAGE - 1)) * STAGE_BYTES;
        uint32_t bufB = bufA + 8192;

        #pragma unroll
        for (int kk = 0; kk < 2; kk++) {
            uint4 af[4];
            uint2 bf[4];
            #pragma unroll
            for (int mt = 0; mt < 4; mt++) {
                uint32_t a = bufA + ((((wm * 4 + mt) * 2 + kk) * 32 + ln) * 16);
                asm volatile("ld.shared.v4.b32 {%0,%1,%2,%3}, [%4];"
                             : "=r"(af[mt].x), "=r"(af[mt].y), "=r"(af[mt].z), "=r"(af[mt].w)
                             : "r"(a));
            }
            #pragma unroll
            for (int nt = 0; nt < 4; nt++) {
                int NT = wn * 4 + nt;
                uint32_t b = bufB + (((NT * 2 + kk) * 32 + ln) * 8);
                asm volatile("ld.shared.v2.b32 {%0,%1}, [%2];"
                             : "=r"(bf[nt].x), "=r"(bf[nt].y) : "r"(b));
            }
            #pragma unroll
            for (int mt = 0; mt < 4; mt++)
                #pragma unroll
                for (int nt = 0; nt < 4; nt++)
                    mma_f16(acc[mt][nt], af[mt].x, af[mt].y, af[mt].z, af[mt].w,
                            bf[nt].x, bf[nt].y);
        }
    }

    int g_  = ln >> 2;
    int t4  = ln & 3;
    #pragma unroll
    for (int nt = 0; nt < 4; nt++) {
        int col = grp * 128 + wn * 32 + nt * 8 + t4 * 2;
        #pragma unroll
        for (int mt = 0; mt < 4; mt++) {
            int row0 = mb * 128 + wm * 64 + mt * 16 + g_;
            if (row0 < N_V)
                *(float2*)(g_P + (size_t)row0 * 512 + col) =
                    make_float2(acc[mt][nt][0], acc[mt][nt][1]);
            if (row0 + 8 < N_V)
                *(float2*)(g_P + (size_t)(row0 + 8) * 512 + col) =
                    make_float2(acc[mt][nt][2], acc[mt][nt][3]);
        }
    }
}

// ---------------------------------------------------------------------------
// K3: inverse angular DFT combine + bias + relu.
// ---------------------------------------------------------------------------
__global__ __launch_bounds__(256)
void combine_kernel(const float* __restrict__ bias, float* __restrict__ out)
{
    int gidx = blockIdx.x * 256 + threadIdx.x;
    int n = gidx >> 6;
    int t = gidx & 63;
    if (n >= N_V) return;

    const float* P = g_P + (size_t)n * 512;
    float P0 = P[t],        P4 = P[64 + t];
    float R1 = P[128 + t],  I1 = P[192 + t];
    float R2 = P[256 + t],  I2 = P[320 + t];
    float R3 = P[384 + t],  I3 = P[448 + t];
    float b = bias[t];

    const float CO1[8] = {1.f, SQ2, 0.f, -SQ2, -1.f, -SQ2, 0.f, SQ2};
    const float SI1[8] = {0.f, SQ2, 1.f, SQ2, 0.f, -SQ2, -1.f, -SQ2};
    const float CO2[8] = {1.f, 0.f, -1.f, 0.f, 1.f, 0.f, -1.f, 0.f};
    const float SI2[8] = {0.f, 1.f, 0.f, -1.f, 0.f, 1.f, 0.f, -1.f};
    const float CO3[8] = {1.f, -SQ2, 0.f, SQ2, -1.f, SQ2, 0.f, -SQ2};
    const float SI3[8] = {0.f, SQ2, -1.f, SQ2, 0.f, -SQ2, 1.f, -SQ2};

    float* orow = out + (size_t)n * NCOL;
    #pragma unroll
    for (int o = 0; o < 8; o++) {
        float sgn = (o & 1) ? -1.f : 1.f;
        float val = 0.125f * (P0 + sgn * P4
                    + 2.f * (R1 * CO1[o] - I1 * SI1[o]
                           + R2 * CO2[o] - I2 * SI2[o]
                           + R3 * CO3[o] - I3 * SI3[o])) + b;
        orow[o * 64 + t] = val > 0.f ? val : 0.f;
    }
}

// ---------------------------------------------------------------------------
// Launch order: convert, build_V, dummy, build_X, gemm, combine
// (build_X = our 4th launch -> captured by ncu -s 5 -c 1 this round).
// Inputs: mesh_signal, bary_coordinates, neighbor_weights, center_weights,
//         bias, interp_coeff
// ---------------------------------------------------------------------------
extern "C" void kernel_launch(void* const* d_in, const int* in_sizes, int n_in,
                              void* d_out, int out_size)
{
    const float* ms    = (const float*)d_in[0];
    const float* bary  = (const float*)d_in[1];
    const float* nw    = (const float*)d_in[2];
    const float* cw    = (const float*)d_in[3];
    const float* bias  = (const float*)d_in[4];
    const float* coeff = (const float*)d_in[5];
    float* out = (float*)d_out;

    cudaFuncSetAttribute(gemm_kernel,
                         cudaFuncAttributeMaxDynamicSharedMemorySize, SMEM_TOTAL);

    convert_ms_kernel<<<(N_V * 32 + 255) / 256, 256>>>(ms);
    build_V_kernel<<<64, 64>>>(nw, cw, coeff);
    dummy_kernel<<<1, 1>>>();
    build_X_kernel<<<MB_N * 64, 512>>>(bary);

    dim3 grid(4, MB_N);
    gemm_kernel<<<grid, 256, SMEM_TOTAL>>>();

    combine_kernel<<<(N_V * 64 + 255) / 256, 256>>>(bias, out);
}

// round 16
// speedup vs baseline: 1.1603x; 1.1430x over previous
#include <cuda_runtime.h>
#include <cuda_fp16.h>
#include <cstdint>

// Problem constants
#define N_V   50000
#define R_    5
#define A_    8
#define RA    40
#define C_    64
#define NCOL  512
#define CH_N  82              // 32-k chunks total: g0:22 (K=704), g1-3:20 (K=640)
#define MB_N  391             // ceil(50048/128)
#define SQ2   0.70710678118654752f

// Scratch (static device arrays — no cudaMalloc allowed)
__device__ __half g_msh[(size_t)N_V * C_];               // 6.4 MB fp16 mesh signal
__device__ __half g_Afrag[(size_t)MB_N * CH_N * 4096];   // ~262 MB freq-domain A frags
__device__ __half g_Bfrag[(size_t)CH_N * 4096];          // 672 KB freq-domain B frags
__device__ float  g_P[(size_t)MB_N * 128 * 512];         // ~102 MB partial products

__device__ __forceinline__ uint32_t smem_u32(const void* p) {
    uint32_t a;
    asm("{ .reg .u64 t; cvta.to.shared.u64 t, %1; cvt.u32.u64 %0, t; }" : "=r"(a) : "l"(p));
    return a;
}
__device__ __forceinline__ int grp_cb(int g) { return g == 0 ? 0 : 2 + g * 20; }

// Dummy: keeps ncu capture slot (our 4th launch) on build_X.
__global__ void dummy_kernel() {}

// K-pre: fp32 -> fp16 mesh signal.
__global__ void convert_ms_kernel(const float* __restrict__ ms)
{
    int i = blockIdx.x * 256 + threadIdx.x;      // half2 index
    if (i < N_V * 32) {
        float2 v = ((const float2*)ms)[i];
        ((__half2*)g_msh)[i] = __floats2half2_rn(v.x, v.y);
    }
}

// 8-point real FFT, e^{-i2*pi*f*a/8}. out: r0,r4,r1,i1,r2,i2,r3,i3
__device__ __forceinline__ void fft8(float x0, float x1, float x2, float x3,
                                     float x4, float x5, float x6, float x7,
                                     float* o)
{
    float a04 = x0 + x4, s04 = x0 - x4;
    float a26 = x2 + x6, s26 = x2 - x6;
    float a15 = x1 + x5, s15 = x1 - x5;
    float a37 = x3 + x7, s37 = x3 - x7;
    o[0] = a04 + a26 + a15 + a37;
    o[1] = a04 + a26 - a15 - a37;
    float u = SQ2 * (s15 - s37);
    float w = SQ2 * (s15 + s37);
    o[2] = s04 + u;
    o[3] = -(w + s26);
    o[4] = a04 - a26;
    o[5] = -(a15 - a37);
    o[6] = s04 - u;
    o[7] = -(w - s26);
}

// B fragment half index
__device__ __forceinline__ size_t bfrag_idx(int cb, int klocal, int j) {
    int kt = klocal >> 5, kl = klocal & 31;
    int kk = kl >> 4, kb = kl & 15;
    int r = kb >> 3, rem = kb & 7, t4 = rem >> 1, e = rem & 1;
    int NT = j >> 3, gn = j & 7;
    int ln = gn * 4 + t4;
    return (size_t)(cb + kt) * 4096 + (size_t)(((NT * 2 + kk) * 32 + ln) * 4 + r * 2 + e);
}

// ---------------------------------------------------------------------------
// K0: fold prior into V (= Weff at o=0), rFFT over alpha, write B fragments.
// ---------------------------------------------------------------------------
__global__ void build_V_kernel(const float* __restrict__ nw,
                               const float* __restrict__ cw,
                               const float* __restrict__ coeff)
{
    int t = blockIdx.x;
    int c = threadIdx.x;

    __shared__ float s_coeff[R_ * A_ * RA];
    for (int i = c; i < R_ * A_ * RA; i += 64) s_coeff[i] = coeff[i];
    __syncthreads();

    float wv[R_][A_];
    #pragma unroll
    for (int r = 0; r < R_; r++)
        #pragma unroll
        for (int a = 0; a < A_; a++)
            wv[r][a] = nw[(((size_t)t * R_ + r) * A_ + a) * C_ + c];

    float v[RA];
    for (int m = 0; m < RA; m++) {
        float acc = 0.f;
        #pragma unroll
        for (int r = 0; r < R_; r++)
            #pragma unroll
            for (int a = 0; a < A_; a++)
                acc += s_coeff[(r * A_ + a) * RA + m] * wv[r][a];
        v[m] = acc;
    }

    #pragma unroll
    for (int rho = 0; rho < R_; rho++) {
        float o[8];
        fft8(v[rho * 8 + 0], v[rho * 8 + 1], v[rho * 8 + 2], v[rho * 8 + 3],
             v[rho * 8 + 4], v[rho * 8 + 5], v[rho * 8 + 6], v[rho * 8 + 7], o);
        int kb = rho * 64 + c;
        __half zero = __float2half_rn(0.f);
        g_Bfrag[bfrag_idx(0, kb,       t     )] = __float2half_rn(o[0]);
        g_Bfrag[bfrag_idx(0, 320 + kb, t     )] = zero;
        g_Bfrag[bfrag_idx(0, kb,       64 + t)] = zero;
        g_Bfrag[bfrag_idx(0, 320 + kb, 64 + t)] = __float2half_rn(o[1]);
        #pragma unroll
        for (int f = 1; f <= 3; f++) {
            float vr = o[f * 2], vi = o[f * 2 + 1];
            int cb = grp_cb(f);
            g_Bfrag[bfrag_idx(cb, kb,       t     )] = __float2half_rn(vr);
            g_Bfrag[bfrag_idx(cb, 320 + kb, t     )] = __float2half_rn(vi);
            g_Bfrag[bfrag_idx(cb, kb,       64 + t)] = __float2half_rn(vi);
            g_Bfrag[bfrag_idx(cb, 320 + kb, 64 + t)] = __float2half_rn(-vr);
        }
    }
    g_Bfrag[bfrag_idx(0, 640 + c, t     )] = __float2half_rn(8.f * cw[t * C_ + c]);
    g_Bfrag[bfrag_idx(0, 640 + c, 64 + t)] = __float2half_rn(0.f);
}

// ---------------------------------------------------------------------------
// K1: fp16 gather (half4 loads) -> smem -> angular rFFT -> fp16 A-fragments.
// One block per vertex PAIR (n, n+8), 512 threads (bit 8 = vertex).
// Gather: 16 m-groups x 16 lane-quads (half4 = 8B loads cover a 128B row).
// ---------------------------------------------------------------------------
__global__ __launch_bounds__(512)
void build_X_kernel(const float* __restrict__ bary)
{
    int bp = blockIdx.x;
    int mb = bp >> 6;
    int q  = bp & 63;
    int MT = q >> 3;
    int gl = q & 7;
    int n0 = mb * 128 + MT * 16 + gl;

    __shared__ float s_row[2][2624];
    __shared__ float sb[2][240];
    int tid = threadIdx.x;
    int v   = tid >> 8;
    int t   = tid & 255;
    int n   = n0 + 8 * v;
    bool ok = n < N_V;

    // bary staging: 60 float4 per vertex
    if (t < 60) {
        float4 bv = ok ? ((const float4*)(bary + (size_t)n * 240))[t]
                       : make_float4(0.f, 0.f, 0.f, 0.f);
        *(float4*)&sb[v][t * 4] = bv;
    }
    __syncthreads();

    if (ok) {
        int q16 = t >> 4;           // 0..15 m-group
        int cl  = t & 15;           // lane-quad: 4 channels
        const uint2* msh4 = (const uint2*)g_msh;   // 8B = 4 halves
        #pragma unroll
        for (int it = 0; it < 3; it++) {
            int m = it * 16 + q16;
            if (m < RA) {
                int i0 = (int)sb[v][m * 6 + 0]; float w0 = sb[v][m * 6 + 1];
                int i1 = (int)sb[v][m * 6 + 2]; float w1 = sb[v][m * 6 + 3];
                int i2 = (int)sb[v][m * 6 + 4]; float w2 = sb[v][m * 6 + 5];
                uint2 u0 = msh4[(size_t)i0 * 16 + cl];
                uint2 u1 = msh4[(size_t)i1 * 16 + cl];
                uint2 u2 = msh4[(size_t)i2 * 16 + cl];
                float2 a0 = __half22float2(*(__half2*)&u0.x);
                float2 b0 = __half22float2(*(__half2*)&u0.y);
                float2 a1 = __half22float2(*(__half2*)&u1.x);
                float2 b1 = __half22float2(*(__half2*)&u1.y);
                float2 a2 = __half22float2(*(__half2*)&u2.x);
                float2 b2 = __half22float2(*(__half2*)&u2.y);
                float4 r;
                r.x = w0 * a0.x + w1 * a1.x + w2 * a2.x;
                r.y = w0 * a0.y + w1 * a1.y + w2 * a2.y;
                r.z = w0 * b0.x + w1 * b1.x + w2 * b2.x;
                r.w = w0 * b0.y + w1 * b1.y + w2 * b2.y;
                *(float4*)&s_row[v][m * C_ + cl * 4] = r;
            }
        }
        if (t < 16) {
            uint2 uc = msh4[(size_t)n * 16 + t];
            float2 c0 = __half22float2(*(__half2*)&uc.x);
            float2 c1 = __half22float2(*(__half2*)&uc.y);
            *(float4*)&s_row[v][2560 + t * 4] = make_float4(c0.x, c0.y, c1.x, c1.y);
        }
    } else {
        for (int i = t; i < 2624; i += 256) s_row[v][i] = 0.f;
    }
    __syncthreads();

    // FFT pass (tasks 0..319 = FFT over alpha; 320..383 move center rows)
    float rg[2][8];
    #pragma unroll
    for (int p = 0; p < 2; p++) {
        int task = t + p * 256;
        if (task < 320) {
            int rho = task >> 6, c = task & 63;
            const float* x = &s_row[v][rho * 512 + c];
            fft8(x[0], x[64], x[128], x[192], x[256], x[320], x[384], x[448], rg[p]);
        } else if (task < 384) {
            rg[p][0] = s_row[v][2560 + (task - 320)];
        }
    }
    __syncthreads();
    #pragma unroll
    for (int p = 0; p < 2; p++) {
        int task = t + p * 256;
        if (task < 320) {
            int rho = task >> 6, c = task & 63;
            int base = rho * 64 + c;
            s_row[v][base]        = rg[p][0];   // Xr0
            s_row[v][320 + base]  = rg[p][1];   // Xr4
            s_row[v][704 + base]  = rg[p][2];   // Xr1
            s_row[v][1024 + base] = rg[p][3];   // Xi1
            s_row[v][1344 + base] = rg[p][4];   // Xr2
            s_row[v][1664 + base] = rg[p][5];   // Xi2
            s_row[v][1984 + base] = rg[p][6];   // Xr3
            s_row[v][2304 + base] = rg[p][7];   // Xi3
        } else if (task < 384) {
            s_row[v][640 + (task - 320)] = rg[p][0];
        }
    }
    __syncthreads();

    // fragment write: 82 chunks x 8 (kk,t4) uint4 per vertex pair.
    // Vectorized float2 LDS; st.global.cs to stream past L2.
    for (int w = tid; w < CH_N * 8; w += 512) {
        int kt = w >> 3;
        int kk = (w >> 2) & 1;
        int t4 = w & 3;
        int k0 = kt * 32 + kk * 16 + t4 * 2;
        float2 p00 = *(float2*)&s_row[0][k0];
        float2 p10 = *(float2*)&s_row[1][k0];
        float2 p01 = *(float2*)&s_row[0][k0 + 8];
        float2 p11 = *(float2*)&s_row[1][k0 + 8];
        __half2 x = __floats2half2_rn(p00.x, p00.y);
        __half2 y = __floats2half2_rn(p10.x, p10.y);
        __half2 z = __floats2half2_rn(p01.x, p01.y);
        __half2 u = __floats2half2_rn(p11.x, p11.y);
        uint4* dst = ((uint4*)(g_Afrag + ((size_t)mb * CH_N + kt) * 4096))
                     + ((MT * 2 + kk) * 32 + gl * 4 + t4);
        asm volatile("st.global.cs.v4.b32 [%0], {%1,%2,%3,%4};"
                     :: "l"(dst), "r"(*(uint32_t*)&x), "r"(*(uint32_t*)&y),
                        "r"(*(uint32_t*)&z), "r"(*(uint32_t*)&u) : "memory");
    }
}

// ---------------------------------------------------------------------------
// K2: per-frequency fp16 GEMM -> partial products P. (unchanged)
// ---------------------------------------------------------------------------
__device__ __forceinline__ void mma_f16(float* c, uint32_t a0, uint32_t a1,
                                        uint32_t a2, uint32_t a3,
                                        uint32_t b0, uint32_t b1)
{
    asm volatile(
        "mma.sync.aligned.m16n8k16.row.col.f32.f16.f16.f32 "
        "{%0,%1,%2,%3}, {%4,%5,%6,%7}, {%8,%9}, {%0,%1,%2,%3};\n"
        : "+f"(c[0]), "+f"(c[1]), "+f"(c[2]), "+f"(c[3])
        : "r"(a0), "r"(a1), "r"(a2), "r"(a3), "r"(b0), "r"(b1));
}
__device__ __forceinline__ void cp16(uint32_t s, const void* g) {
    asm volatile("cp.async.cg.shared.global [%0], [%1], 16;" :: "r"(s), "l"(g));
}

#define STAGE_BYTES 16384
#define NSTAGE      4
#define SMEM_TOTAL  (NSTAGE * STAGE_BYTES)   // 64KB

__global__ __launch_bounds__(256, 2)
void gemm_kernel()
{
    extern __shared__ char smem[];
    uint32_t sbase = smem_u32(smem);

    int tid  = threadIdx.x;
    int warp = tid >> 5;
    int ln   = tid & 31;
    int wm   = warp >> 2;
    int wn   = warp & 3;
    int grp  = blockIdx.x;
    int mb   = blockIdx.y;

    int cb  = grp_cb(grp);
    int ktn = (grp == 0) ? 22 : 20;

    const uint4* Ag = (const uint4*)(g_Afrag + ((size_t)mb * CH_N + cb) * 4096);
    const uint4* Bg = (const uint4*)(g_Bfrag + (size_t)cb * 4096);

    auto issue = [&](int s) {
        uint32_t dst = sbase + (uint32_t)(s & (NSTAGE - 1)) * STAGE_BYTES;
        const uint4* As = Ag + (size_t)s * 512;
        cp16(dst + tid * 16, As + tid);
        cp16(dst + (tid + 256) * 16, As + tid + 256);
        const uint4* Bs = Bg + (size_t)s * 512;
        cp16(dst + 8192 + tid * 16, Bs + tid);
        cp16(dst + 8192 + (tid + 256) * 16, Bs + tid + 256);
    };

    issue(0);
    asm volatile("cp.async.commit_group;" ::: "memory");
    issue(1);
    asm volatile("cp.async.commit_group;" ::: "memory");
    issue(2);
    asm volatile("cp.async.commit_group;" ::: "memory");

    float acc[4][4][4];
    #pragma unroll
    for (int mt = 0; mt < 4; mt++)
        #pragma unroll
        for (int nt = 0; nt < 4; nt++)
            #pragma unroll
            for (int i = 0; i < 4; i++) acc[mt][nt][i] = 0.f;

    for (int kt = 0; kt < ktn; kt++) {
        asm volatile("cp.async.wait_group 2;" ::: "memory");
        __syncthreads();

        if (kt + 3 < ktn) issue(kt + 3);
        asm volatile("cp.async.commit_group;" ::: "memory");

        uint32_t bufA = sbase + (uint32_t)(kt & (NSTAGE - 1)) * STAGE_BYTES;
        uint32_t bufB = bufA + 8192;

        #pragma unroll
        for (int kk = 0; kk < 2; kk++) {
            uint4 af[4];
            uint2 bf[4];
            #pragma unroll
            for (int mt = 0; mt < 4; mt++) {
                uint32_t a = bufA + ((((wm * 4 + mt) * 2 + kk) * 32 + ln) * 16);
                asm volatile("ld.shared.v4.b32 {%0,%1,%2,%3}, [%4];"
                             : "=r"(af[mt].x), "=r"(af[mt].y), "=r"(af[mt].z), "=r"(af[mt].w)
                             : "r"(a));
            }
            #pragma unroll
            for (int nt = 0; nt < 4; nt++) {
                int NT = wn * 4 + nt;
                uint32_t b = bufB + (((NT * 2 + kk) * 32 + ln) * 8);
                asm volatile("ld.shared.v2.b32 {%0,%1}, [%2];"
                             : "=r"(bf[nt].x), "=r"(bf[nt].y) : "r"(b));
            }
            #pragma unroll
            for (int mt = 0; mt < 4; mt++)
                #pragma unroll
                for (int nt = 0; nt < 4; nt++)
                    mma_f16(acc[mt][nt], af[mt].x, af[mt].y, af[mt].z, af[mt].w,
                            bf[nt].x, bf[nt].y);
        }
    }

    int g_  = ln >> 2;
    int t4  = ln & 3;
    #pragma unroll
    for (int nt = 0; nt < 4; nt++) {
        int col = grp * 128 + wn * 32 + nt * 8 + t4 * 2;
        #pragma unroll
        for (int mt = 0; mt < 4; mt++) {
            int row0 = mb * 128 + wm * 64 + mt * 16 + g_;
            if (row0 < N_V)
                *(float2*)(g_P + (size_t)row0 * 512 + col) =
                    make_float2(acc[mt][nt][0], acc[mt][nt][1]);
            if (row0 + 8 < N_V)
                *(float2*)(g_P + (size_t)(row0 + 8) * 512 + col) =
                    make_float2(acc[mt][nt][2], acc[mt][nt][3]);
        }
    }
}

// ---------------------------------------------------------------------------
// K3: inverse angular DFT combine + bias + relu.
// ---------------------------------------------------------------------------
__global__ __launch_bounds__(256)
void combine_kernel(const float* __restrict__ bias, float* __restrict__ out)
{
    int gidx = blockIdx.x * 256 + threadIdx.x;
    int n = gidx >> 6;
    int t = gidx & 63;
    if (n >= N_V) return;

    const float* P = g_P + (size_t)n * 512;
    float P0 = P[t],        P4 = P[64 + t];
    float R1 = P[128 + t],  I1 = P[192 + t];
    float R2 = P[256 + t],  I2 = P[320 + t];
    float R3 = P[384 + t],  I3 = P[448 + t];
    float b = bias[t];

    const float CO1[8] = {1.f, SQ2, 0.f, -SQ2, -1.f, -SQ2, 0.f, SQ2};
    const float SI1[8] = {0.f, SQ2, 1.f, SQ2, 0.f, -SQ2, -1.f, -SQ2};
    const float CO2[8] = {1.f, 0.f, -1.f, 0.f, 1.f, 0.f, -1.f, 0.f};
    const float SI2[8] = {0.f, 1.f, 0.f, -1.f, 0.f, 1.f, 0.f, -1.f};
    const float CO3[8] = {1.f, -SQ2, 0.f, SQ2, -1.f, SQ2, 0.f, -SQ2};
    const float SI3[8] = {0.f, SQ2, -1.f, SQ2, 0.f, -SQ2, 1.f, -SQ2};

    float* orow = out + (size_t)n * NCOL;
    #pragma unroll
    for (int o = 0; o < 8; o++) {
        float sgn = (o & 1) ? -1.f : 1.f;
        float val = 0.125f * (P0 + sgn * P4
                    + 2.f * (R1 * CO1[o] - I1 * SI1[o]
                           + R2 * CO2[o] - I2 * SI2[o]
                           + R3 * CO3[o] - I3 * SI3[o])) + b;
        orow[o * 64 + t] = val > 0.f ? val : 0.f;
    }
}

// ---------------------------------------------------------------------------
// Launch order: convert, build_V, dummy, build_X, gemm, combine
// (build_X = our 4th launch -> captured by ncu -s 5 -c 1).
// Inputs: mesh_signal, bary_coordinates, neighbor_weights, center_weights,
//         bias, interp_coeff
// ---------------------------------------------------------------------------
extern "C" void kernel_launch(void* const* d_in, const int* in_sizes, int n_in,
                              void* d_out, int out_size)
{
    const float* ms    = (const float*)d_in[0];
    const float* bary  = (const float*)d_in[1];
    const float* nw    = (const float*)d_in[2];
    const float* cw    = (const float*)d_in[3];
    const float* bias  = (const float*)d_in[4];
    const float* coeff = (const float*)d_in[5];
    float* out = (float*)d_out;

    cudaFuncSetAttribute(gemm_kernel,
                         cudaFuncAttributeMaxDynamicSharedMemorySize, SMEM_TOTAL);

    convert_ms_kernel<<<(N_V * 32 + 255) / 256, 256>>>(ms);
    build_V_kernel<<<64, 64>>>(nw, cw, coeff);
    dummy_kernel<<<1, 1>>>();
    build_X_kernel<<<MB_N * 64, 512>>>(bary);

    dim3 grid(4, MB_N);
    gemm_kernel<<<grid, 256, SMEM_TOTAL>>>();

    combine_kernel<<<(N_V * 64 + 255) / 256, 256>>>(bias, out);
}

// round 17
// speedup vs baseline: 1.2542x; 1.0809x over previous
#include <cuda_runtime.h>
#include <cuda_fp16.h>
#include <cstdint>

// Problem constants
#define N_V   50000
#define R_    5
#define A_    8
#define RA    40
#define C_    64
#define NCOL  512
#define CH_N  82              // 32-k chunks total: g0:22 (K=704), g1-3:20 (K=640)
#define MB_N  391             // ceil(50048/128)
#define SQ2   0.70710678118654752f

// Scratch (static device arrays — no cudaMalloc allowed)
__device__ __half g_msh[(size_t)N_V * C_];               // 6.4 MB fp16 mesh signal
__device__ __half g_Afrag[(size_t)MB_N * CH_N * 4096];   // ~262 MB freq-domain A frags
__device__ __half g_Bfrag[(size_t)CH_N * 4096];          // 672 KB freq-domain B frags
__device__ float  g_P[(size_t)MB_N * 128 * 512];         // ~102 MB partial products

__device__ __forceinline__ uint32_t smem_u32(const void* p) {
    uint32_t a;
    asm("{ .reg .u64 t; cvta.to.shared.u64 t, %1; cvt.u32.u64 %0, t; }" : "=r"(a) : "l"(p));
    return a;
}
__device__ __forceinline__ int grp_cb(int g) { return g == 0 ? 0 : 2 + g * 20; }

// Dummy: keeps ncu capture slot (our 4th launch) on build_X.
__global__ void dummy_kernel() {}

// K-pre: fp32 -> fp16 mesh signal.
__global__ void convert_ms_kernel(const float* __restrict__ ms)
{
    int i = blockIdx.x * 256 + threadIdx.x;      // half2 index
    if (i < N_V * 32) {
        float2 v = ((const float2*)ms)[i];
        ((__half2*)g_msh)[i] = __floats2half2_rn(v.x, v.y);
    }
}

// 8-point real FFT (fp32, used by build_V). out: r0,r4,r1,i1,r2,i2,r3,i3
__device__ __forceinline__ void fft8(float x0, float x1, float x2, float x3,
                                     float x4, float x5, float x6, float x7,
                                     float* o)
{
    float a04 = x0 + x4, s04 = x0 - x4;
    float a26 = x2 + x6, s26 = x2 - x6;
    float a15 = x1 + x5, s15 = x1 - x5;
    float a37 = x3 + x7, s37 = x3 - x7;
    o[0] = a04 + a26 + a15 + a37;
    o[1] = a04 + a26 - a15 - a37;
    float u = SQ2 * (s15 - s37);
    float w = SQ2 * (s15 + s37);
    o[2] = s04 + u;
    o[3] = -(w + s26);
    o[4] = a04 - a26;
    o[5] = -(a15 - a37);
    o[6] = s04 - u;
    o[7] = -(w - s26);
}

// B fragment half index
__device__ __forceinline__ size_t bfrag_idx(int cb, int klocal, int j) {
    int kt = klocal >> 5, kl = klocal & 31;
    int kk = kl >> 4, kb = kl & 15;
    int r = kb >> 3, rem = kb & 7, t4 = rem >> 1, e = rem & 1;
    int NT = j >> 3, gn = j & 7;
    int ln = gn * 4 + t4;
    return (size_t)(cb + kt) * 4096 + (size_t)(((NT * 2 + kk) * 32 + ln) * 4 + r * 2 + e);
}

// ---------------------------------------------------------------------------
// K0: fold prior into V (= Weff at o=0), rFFT over alpha, write B fragments.
// (fp32 path — tiny kernel, precision kept.)
// ---------------------------------------------------------------------------
__global__ void build_V_kernel(const float* __restrict__ nw,
                               const float* __restrict__ cw,
                               const float* __restrict__ coeff)
{
    int t = blockIdx.x;
    int c = threadIdx.x;

    __shared__ float s_coeff[R_ * A_ * RA];
    for (int i = c; i < R_ * A_ * RA; i += 64) s_coeff[i] = coeff[i];
    __syncthreads();

    float wv[R_][A_];
    #pragma unroll
    for (int r = 0; r < R_; r++)
        #pragma unroll
        for (int a = 0; a < A_; a++)
            wv[r][a] = nw[(((size_t)t * R_ + r) * A_ + a) * C_ + c];

    float v[RA];
    for (int m = 0; m < RA; m++) {
        float acc = 0.f;
        #pragma unroll
        for (int r = 0; r < R_; r++)
            #pragma unroll
            for (int a = 0; a < A_; a++)
                acc += s_coeff[(r * A_ + a) * RA + m] * wv[r][a];
        v[m] = acc;
    }

    #pragma unroll
    for (int rho = 0; rho < R_; rho++) {
        float o[8];
        fft8(v[rho * 8 + 0], v[rho * 8 + 1], v[rho * 8 + 2], v[rho * 8 + 3],
             v[rho * 8 + 4], v[rho * 8 + 5], v[rho * 8 + 6], v[rho * 8 + 7], o);
        int kb = rho * 64 + c;
        __half zero = __float2half_rn(0.f);
        g_Bfrag[bfrag_idx(0, kb,       t     )] = __float2half_rn(o[0]);
        g_Bfrag[bfrag_idx(0, 320 + kb, t     )] = zero;
        g_Bfrag[bfrag_idx(0, kb,       64 + t)] = zero;
        g_Bfrag[bfrag_idx(0, 320 + kb, 64 + t)] = __float2half_rn(o[1]);
        #pragma unroll
        for (int f = 1; f <= 3; f++) {
            float vr = o[f * 2], vi = o[f * 2 + 1];
            int cb = grp_cb(f);
            g_Bfrag[bfrag_idx(cb, kb,       t     )] = __float2half_rn(vr);
            g_Bfrag[bfrag_idx(cb, 320 + kb, t     )] = __float2half_rn(vi);
            g_Bfrag[bfrag_idx(cb, kb,       64 + t)] = __float2half_rn(vi);
            g_Bfrag[bfrag_idx(cb, 320 + kb, 64 + t)] = __float2half_rn(-vr);
        }
    }
    g_Bfrag[bfrag_idx(0, 640 + c, t     )] = __float2half_rn(8.f * cw[t * C_ + c]);
    g_Bfrag[bfrag_idx(0, 640 + c, 64 + t)] = __float2half_rn(0.f);
}

// ---------------------------------------------------------------------------
// K1: all-fp16 build_X. Gather with HFMA2 interp -> half2 smem -> half2 FFT
// -> fragment writes are pure half2 moves (zero conversions).
// One block per vertex PAIR (n, n+8), 512 threads (bit 8 = vertex).
// half2 layout per vertex (1312 half2): time-domain m*32+cp; after FFT:
// Xr0@0 Xr4@160 center@320 Xr1@352 Xi1@512 Xr2@672 Xi2@832 Xr3@992 Xi3@1152.
// ---------------------------------------------------------------------------
__global__ __launch_bounds__(512)
void build_X_kernel(const float* __restrict__ bary)
{
    int bp = blockIdx.x;
    int mb = bp >> 6;
    int q  = bp & 63;
    int MT = q >> 3;
    int gl = q & 7;
    int n0 = mb * 128 + MT * 16 + gl;

    __shared__ __half2 s_h2[2][1312];
    __shared__ float sb[2][240];
    int tid = threadIdx.x;
    int v   = tid >> 8;
    int t   = tid & 255;
    int n   = n0 + 8 * v;
    bool ok = n < N_V;

    // bary staging: 60 float4 per vertex
    if (t < 60) {
        float4 bv = ok ? ((const float4*)(bary + (size_t)n * 240))[t]
                       : make_float4(0.f, 0.f, 0.f, 0.f);
        *(float4*)&sb[v][t * 4] = bv;
    }
    __syncthreads();

    if (ok) {
        int q16 = t >> 4;           // 0..15 m-group
        int cl  = t & 15;           // lane-quad: 4 channels (uint2 = 2 half2)
        const uint2* msh4 = (const uint2*)g_msh;
        #pragma unroll
        for (int it = 0; it < 3; it++) {
            int m = it * 16 + q16;
            if (m < RA) {
                float2 p0 = *(float2*)&sb[v][m * 6 + 0];
                float2 p1 = *(float2*)&sb[v][m * 6 + 2];
                float2 p2 = *(float2*)&sb[v][m * 6 + 4];
                int i0 = (int)p0.x; __half2 w0 = __float2half2_rn(p0.y);
                int i1 = (int)p1.x; __half2 w1 = __float2half2_rn(p1.y);
                int i2 = (int)p2.x; __half2 w2 = __float2half2_rn(p2.y);
                uint2 u0 = msh4[(size_t)i0 * 16 + cl];
                uint2 u1 = msh4[(size_t)i1 * 16 + cl];
                uint2 u2 = msh4[(size_t)i2 * 16 + cl];
                __half2 ra = __hfma2(w0, *(__half2*)&u0.x,
                              __hfma2(w1, *(__half2*)&u1.x,
                               __hmul2(w2, *(__half2*)&u2.x)));
                __half2 rb = __hfma2(w0, *(__half2*)&u0.y,
                              __hfma2(w1, *(__half2*)&u1.y,
                               __hmul2(w2, *(__half2*)&u2.y)));
                uint2 st;
                st.x = *(uint32_t*)&ra;
                st.y = *(uint32_t*)&rb;
                *(uint2*)&s_h2[v][m * 32 + cl * 2] = st;
            }
        }
        if (t < 16) {
            uint2 uc = msh4[(size_t)n * 16 + t];
            *(uint2*)&s_h2[v][1280 + t * 2] = uc;
        }
    } else {
        for (int i = t; i < 1312; i += 256) s_h2[v][i] = __float2half2_rn(0.f);
    }
    __syncthreads();

    // half2 FFT: tasks t<160 -> (rho = t>>5, cp = t&31); t in [160,192) move center.
    __half2 og[8];
    __half2 cmov;
    bool isfft = t < 160;
    if (isfft) {
        int rho = t >> 5, cp = t & 31;
        const __half2* x = &s_h2[v][rho * 256 + cp];
        __half2 x0 = x[0],   x1 = x[32],  x2 = x[64],  x3 = x[96];
        __half2 x4 = x[128], x5 = x[160], x6 = x[192], x7 = x[224];
        __half2 a04 = __hadd2(x0, x4), s04 = __hsub2(x0, x4);
        __half2 a26 = __hadd2(x2, x6), s26 = __hsub2(x2, x6);
        __half2 a15 = __hadd2(x1, x5), s15 = __hsub2(x1, x5);
        __half2 a37 = __hadd2(x3, x7), s37 = __hsub2(x3, x7);
        __half2 e0 = __hadd2(a04, a26), e1 = __hadd2(a15, a37);
        og[0] = __hadd2(e0, e1);
        og[1] = __hsub2(e0, e1);
        __half2 sq2h = __float2half2_rn(SQ2);
        __half2 uu = __hmul2(sq2h, __hsub2(s15, s37));
        __half2 ww = __hmul2(sq2h, __hadd2(s15, s37));
        og[2] = __hadd2(s04, uu);
        og[3] = __hneg2(__hadd2(ww, s26));
        og[4] = __hsub2(a04, a26);
        og[5] = __hsub2(a37, a15);     // -(a15-a37)
        og[6] = __hsub2(s04, uu);
        og[7] = __hsub2(s26, ww);      // -(w-s26)
    } else if (t < 192) {
        cmov = s_h2[v][1280 + (t - 160)];
    }
    __syncthreads();
    if (isfft) {
        int rho = t >> 5, cp = t & 31;
        int base = rho * 32 + cp;
        s_h2[v][base]         = og[0];   // Xr0
        s_h2[v][160 + base]   = og[1];   // Xr4
        s_h2[v][352 + base]   = og[2];   // Xr1
        s_h2[v][512 + base]   = og[3];   // Xi1
        s_h2[v][672 + base]   = og[4];   // Xr2
        s_h2[v][832 + base]   = og[5];   // Xi2
        s_h2[v][992 + base]   = og[6];   // Xr3
        s_h2[v][1152 + base]  = og[7];   // Xi3
    } else if (t < 192) {
        s_h2[v][320 + (t - 160)] = cmov; // center
    }
    __syncthreads();

    // fragment write: pure half2 moves, st.global.cs streaming
    for (int w = tid; w < CH_N * 8; w += 512) {
        int kt = w >> 3;
        int kk = (w >> 2) & 1;
        int t4 = w & 3;
        int h  = kt * 16 + kk * 8 + t4;
        uint32_t x = *(uint32_t*)&s_h2[0][h];
        uint32_t y = *(uint32_t*)&s_h2[1][h];
        uint32_t z = *(uint32_t*)&s_h2[0][h + 4];
        uint32_t u = *(uint32_t*)&s_h2[1][h + 4];
        uint4* dst = ((uint4*)(g_Afrag + ((size_t)mb * CH_N + kt) * 4096))
                     + ((MT * 2 + kk) * 32 + gl * 4 + t4);
        asm volatile("st.global.cs.v4.b32 [%0], {%1,%2,%3,%4};"
                     :: "l"(dst), "r"(x), "r"(y), "r"(z), "r"(u) : "memory");
    }
}

// ---------------------------------------------------------------------------
// K2: per-frequency fp16 GEMM -> partial products P. (unchanged)
// ---------------------------------------------------------------------------
__device__ __forceinline__ void mma_f16(float* c, uint32_t a0, uint32_t a1,
                                        uint32_t a2, uint32_t a3,
                                        uint32_t b0, uint32_t b1)
{
    asm volatile(
        "mma.sync.aligned.m16n8k16.row.col.f32.f16.f16.f32 "
        "{%0,%1,%2,%3}, {%4,%5,%6,%7}, {%8,%9}, {%0,%1,%2,%3};\n"
        : "+f"(c[0]), "+f"(c[1]), "+f"(c[2]), "+f"(c[3])
        : "r"(a0), "r"(a1), "r"(a2), "r"(a3), "r"(b0), "r"(b1));
}
__device__ __forceinline__ void cp16(uint32_t s, const void* g) {
    asm volatile("cp.async.cg.shared.global [%0], [%1], 16;" :: "r"(s), "l"(g));
}

#define STAGE_BYTES 16384
#define NSTAGE      4
#define SMEM_TOTAL  (NSTAGE * STAGE_BYTES)   // 64KB

__global__ __launch_bounds__(256, 2)
void gemm_kernel()
{
    extern __shared__ char smem[];
    uint32_t sbase = smem_u32(smem);

    int tid  = threadIdx.x;
    int warp = tid >> 5;
    int ln   = tid & 31;
    int wm   = warp >> 2;
    int wn   = warp & 3;
    int grp  = blockIdx.x;
    int mb   = blockIdx.y;

    int cb  = grp_cb(grp);
    int ktn = (grp == 0) ? 22 : 20;

    const uint4* Ag = (const uint4*)(g_Afrag + ((size_t)mb * CH_N + cb) * 4096);
    const uint4* Bg = (const uint4*)(g_Bfrag + (size_t)cb * 4096);

    auto issue = [&](int s) {
        uint32_t dst = sbase + (uint32_t)(s & (NSTAGE - 1)) * STAGE_BYTES;
        const uint4* As = Ag + (size_t)s * 512;
        cp16(dst + tid * 16, As + tid);
        cp16(dst + (tid + 256) * 16, As + tid + 256);
        const uint4* Bs = Bg + (size_t)s * 512;
        cp16(dst + 8192 + tid * 16, Bs + tid);
        cp16(dst + 8192 + (tid + 256) * 16, Bs + tid + 256);
    };

    issue(0);
    asm volatile("cp.async.commit_group;" ::: "memory");
    issue(1);
    asm volatile("cp.async.commit_group;" ::: "memory");
    issue(2);
    asm volatile("cp.async.commit_group;" ::: "memory");

    float acc[4][4][4];
    #pragma unroll
    for (int mt = 0; mt < 4; mt++)
        #pragma unroll
        for (int nt = 0; nt < 4; nt++)
            #pragma unroll
            for (int i = 0; i < 4; i++) acc[mt][nt][i] = 0.f;

    for (int kt = 0; kt < ktn; kt++) {
        asm volatile("cp.async.wait_group 2;" ::: "memory");
        __syncthreads();

        if (kt + 3 < ktn) issue(kt + 3);
        asm volatile("cp.async.commit_group;" ::: "memory");

        uint32_t bufA = sbase + (uint32_t)(kt & (NSTAGE - 1)) * STAGE_BYTES;
        uint32_t bufB = bufA + 8192;

        #pragma unroll
        for (int kk = 0; kk < 2; kk++) {
            uint4 af[4];
            uint2 bf[4];
            #pragma unroll
            for (int mt = 0; mt < 4; mt++) {
                uint32_t a = bufA + ((((wm * 4 + mt) * 2 + kk) * 32 + ln) * 16);
                asm volatile("ld.shared.v4.b32 {%0,%1,%2,%3}, [%4];"
                             : "=r"(af[mt].x), "=r"(af[mt].y), "=r"(af[mt].z), "=r"(af[mt].w)
                             : "r"(a));
            }
            #pragma unroll
            for (int nt = 0; nt < 4; nt++) {
                int NT = wn * 4 + nt;
                uint32_t b = bufB + (((NT * 2 + kk) * 32 + ln) * 8);
                asm volatile("ld.shared.v2.b32 {%0,%1}, [%2];"
                             : "=r"(bf[nt].x), "=r"(bf[nt].y) : "r"(b));
            }
            #pragma unroll
            for (int mt = 0; mt < 4; mt++)
                #pragma unroll
                for (int nt = 0; nt < 4; nt++)
                    mma_f16(acc[mt][nt], af[mt].x, af[mt].y, af[mt].z, af[mt].w,
                            bf[nt].x, bf[nt].y);
        }
    }

    int g_  = ln >> 2;
    int t4  = ln & 3;
    #pragma unroll
    for (int nt = 0; nt < 4; nt++) {
        int col = grp * 128 + wn * 32 + nt * 8 + t4 * 2;
        #pragma unroll
        for (int mt = 0; mt < 4; mt++) {
            int row0 = mb * 128 + wm * 64 + mt * 16 + g_;
            if (row0 < N_V)
                *(float2*)(g_P + (size_t)row0 * 512 + col) =
                    make_float2(acc[mt][nt][0], acc[mt][nt][1]);
            if (row0 + 8 < N_V)
                *(float2*)(g_P + (size_t)(row0 + 8) * 512 + col) =
                    make_float2(acc[mt][nt][2], acc[mt][nt][3]);
        }
    }
}

// ---------------------------------------------------------------------------
// K3: inverse angular DFT combine + bias + relu.
// ---------------------------------------------------------------------------
__global__ __launch_bounds__(256)
void combine_kernel(const float* __restrict__ bias, float* __restrict__ out)
{
    int gidx = blockIdx.x * 256 + threadIdx.x;
    int n = gidx >> 6;
    int t = gidx & 63;
    if (n >= N_V) return;

    const float* P = g_P + (size_t)n * 512;
    float P0 = P[t],        P4 = P[64 + t];
    float R1 = P[128 + t],  I1 = P[192 + t];
    float R2 = P[256 + t],  I2 = P[320 + t];
    float R3 = P[384 + t],  I3 = P[448 + t];
    float b = bias[t];

    const float CO1[8] = {1.f, SQ2, 0.f, -SQ2, -1.f, -SQ2, 0.f, SQ2};
    const float SI1[8] = {0.f, SQ2, 1.f, SQ2, 0.f, -SQ2, -1.f, -SQ2};
    const float CO2[8] = {1.f, 0.f, -1.f, 0.f, 1.f, 0.f, -1.f, 0.f};
    const float SI2[8] = {0.f, 1.f, 0.f, -1.f, 0.f, 1.f, 0.f, -1.f};
    const float CO3[8] = {1.f, -SQ2, 0.f, SQ2, -1.f, SQ2, 0.f, -SQ2};
    const float SI3[8] = {0.f, SQ2, -1.f, SQ2, 0.f, -SQ2, 1.f, -SQ2};

    float* orow = out + (size_t)n * NCOL;
    #pragma unroll
    for (int o = 0; o < 8; o++) {
        float sgn = (o & 1) ? -1.f : 1.f;
        float val = 0.125f * (P0 + sgn * P4
                    + 2.f * (R1 * CO1[o] - I1 * SI1[o]
                           + R2 * CO2[o] - I2 * SI2[o]
                           + R3 * CO3[o] - I3 * SI3[o])) + b;
        orow[o * 64 + t] = val > 0.f ? val : 0.f;
    }
}

// ---------------------------------------------------------------------------
// Launch order: convert, build_V, dummy, build_X, gemm, combine
// (build_X = our 4th launch -> captured by ncu -s 5 -c 1).
// Inputs: mesh_signal, bary_coordinates, neighbor_weights, center_weights,
//         bias, interp_coeff
// ---------------------------------------------------------------------------
extern "C" void kernel_launch(void* const* d_in, const int* in_sizes, int n_in,
                              void* d_out, int out_size)
{
    const float* ms    = (const float*)d_in[0];
    const float* bary  = (const float*)d_in[1];
    const float* nw    = (const float*)d_in[2];
    const float* cw    = (const float*)d_in[3];
    const float* bias  = (const float*)d_in[4];
    const float* coeff = (const float*)d_in[5];
    float* out = (float*)d_out;

    cudaFuncSetAttribute(gemm_kernel,
                         cudaFuncAttributeMaxDynamicSharedMemorySize, SMEM_TOTAL);

    convert_ms_kernel<<<(N_V * 32 + 255) / 256, 256>>>(ms);
    build_V_kernel<<<64, 64>>>(nw, cw, coeff);
    dummy_kernel<<<1, 1>>>();
    build_X_kernel<<<MB_N * 64, 512>>>(bary);

    dim3 grid(4, MB_N);
    gemm_kernel<<<grid, 256, SMEM_TOTAL>>>();

    combine_kernel<<<(N_V * 64 + 255) / 256, 256>>>(bias, out);
}